// round 17
// baseline (speedup 1.0000x reference)
#include <cuda_runtime.h>
#include <cuda_fp16.h>
#include <math.h>
#include <stdint.h>

#define DIMM 768
#define HEADS 16
#define DH 48
#define NB 8
#define NSEQ 1024
#define ROWS 8192            // NB*NSEQ
#define QKVC 2304            // 3*DIMM
#define SLICE_SZ 49152       // NSEQ*DH
#define HEAD_BLK 786432      // HEADS*NSEQ*DH
#define THIRD 6291456        // NB*HEAD_BLK
// Q pre-scale: ATT_SCALE * log2(e) folded into Q fragments; softmax uses ex2.
#define QSCALE 0.20823030778170076f

// ---------------- scratch (__device__ globals; no allocation allowed) ------
__device__ __half g_qkvhi[ROWS * QKVC];      // qkv fp16 (GEMM1 out)
__device__ __half g_xh[ROWS * DIMM];         // x fp16 (single precision)
__device__ __half g_ch[ROWS * DIMM];         // context fp16 (attn out)
__device__ __half g_wqh[QKVC * DIMM];        // Wqkv^T fp16 [2304,768]
__device__ __half g_woh[DIMM * DIMM];        // Wo^T fp16   [768,768]

// ---------------- PTX helpers (arch-agnostic: sm_80+ features only) --------
__device__ __forceinline__ uint32_t smem_u32(const void* p) {
    uint32_t a;
    asm("{ .reg .u64 t; cvta.to.shared.u64 t, %1; cvt.u32.u64 %0, t; }"
        : "=r"(a) : "l"(p));
    return a;
}
__device__ __forceinline__ float ex2f(float x) {
    float r;
    asm("ex2.approx.ftz.f32 %0, %1;" : "=f"(r) : "f"(x));
    return r;
}
#define LDSM_X4(r0, r1, r2, r3, addr) \
    asm volatile("ldmatrix.sync.aligned.m8n8.x4.shared.b16 {%0,%1,%2,%3}, [%4];" \
                 : "=r"(r0), "=r"(r1), "=r"(r2), "=r"(r3) : "r"(addr))
#define LDSM_X4T(r0, r1, r2, r3, addr) \
    asm volatile("ldmatrix.sync.aligned.m8n8.x4.trans.shared.b16 {%0,%1,%2,%3}, [%4];" \
                 : "=r"(r0), "=r"(r1), "=r"(r2), "=r"(r3) : "r"(addr))
#define MMA_F16(c, a, b) \
    asm volatile("mma.sync.aligned.m16n8k16.row.col.f32.f16.f16.f32 " \
                 "{%0,%1,%2,%3},{%4,%5,%6,%7},{%8,%9},{%0,%1,%2,%3};" \
                 : "+f"((c)[0]), "+f"((c)[1]), "+f"((c)[2]), "+f"((c)[3]) \
                 : "r"((a)[0]), "r"((a)[1]), "r"((a)[2]), "r"((a)[3]), \
                   "r"((b)[0]), "r"((b)[1]))
#define CP_ASYNC16(s, g) \
    asm volatile("cp.async.cg.shared.global [%0], [%1], 16;" :: "r"(s), "l"(g))
#define CP_COMMIT() asm volatile("cp.async.commit_group;" ::: "memory")
#define CP_WAIT1()  asm volatile("cp.async.wait_group 1;" ::: "memory")
#define CP_WAIT0()  asm volatile("cp.async.wait_group 0;" ::: "memory")

__device__ __forceinline__ uint32_t packh2(float a, float b) {
    __half2 t;
    t.x = __float2half_rn(a);
    t.y = __float2half_rn(b);
    return *(uint32_t*)&t;
}

// ---------------------------------------------------------------------------
// fp16 GEMM on mma.sync: C = A @ B^T (+bias). BM=IM*32, BN=128, BK=32,
// 8 warps, 3-stage pipeline, x4 B-fetch (both k-slices per LDSM).
// IM=4: 128-row tiles (GEMM1). IM=2: 64-row tiles (GEMM2, kills wave tail:
// grid 384 -> 768 CTAs over 296 slots).
// ---------------------------------------------------------------------------
#define BK 32
#define ROW_BYTES 80
#define TILE_BYTES (128 * ROW_BYTES)       // 10240 (A region sized for IM=4)
#define STAGE_BYTES (3 * TILE_BYTES)       // 30720 (A, [pad], B) layout kept
#define NSTAGE 3
#define GEMM_SMEM (NSTAGE * STAGE_BYTES)   // 92160

template<int IM>
__device__ __forceinline__ void stage_load(
    uint32_t sbyte, const __half* s0, const __half* s2,
    int K, long kOff, int tid)
{
    // A tile: IM*32 rows x 4 16B-chunks = IM*128 chunks
    #pragma unroll
    for (int t = 0; t < IM / 2; ++t) {
        const int ch = tid * (IM / 2) + t;
        const int row = ch >> 2;
        const int cc = ch & 3;
        CP_ASYNC16(sbyte + row * ROW_BYTES + cc * 16,
                   s0 + (long)row * K + kOff + cc * 8);
    }
    // B tile: 128 rows x 4 chunks = 512 chunks
    #pragma unroll
    for (int t = 0; t < 2; ++t) {
        const int ch = tid * 2 + t;
        const int row = ch >> 2;
        const int cc = ch & 3;
        CP_ASYNC16(sbyte + 2u * TILE_BYTES + row * ROW_BYTES + cc * 16,
                   s2 + (long)row * K + kOff + cc * 8);
    }
}

template<int IM>
__global__ __launch_bounds__(256, 2)
void mma_gemm(const __half* __restrict__ A, const __half* __restrict__ B,
              const float* __restrict__ bias, float* __restrict__ C,
              __half* __restrict__ Ohi,
              int M, int Nc, int K)
{
    extern __shared__ char smem[];
    const uint32_t sb = smem_u32(smem);
    const int tid = threadIdx.x;
    const int wid = tid >> 5;
    const int lane = tid & 31;
    const int wr = wid >> 2;
    const int wc = wid & 3;
    const int rowBase = blockIdx.y * (IM * 32);
    const int colBase = blockIdx.x << 7;
    const int nch = K / BK;

    const __half* pA = A + (long)rowBase * K;
    const __half* pB = B + (long)colBase * K;

    const int r8 = lane & 7;
    const int quad = lane >> 3;
    const int aRow = wr * (IM * 16) + (quad & 1) * 8 + r8;
    const int aColB = ((quad >> 1) * 8) * 2;
    const int bRow = wc * 32 + (lane & 7);
    const int bColB4 = (lane >> 3) * 16;

    float acc[IM][4][4];
    #pragma unroll
    for (int i = 0; i < IM; ++i)
        #pragma unroll
        for (int j = 0; j < 4; ++j)
            #pragma unroll
            for (int r = 0; r < 4; ++r) acc[i][j][r] = 0.f;

    // prologue: stages 0, 1 in flight
    stage_load<IM>(sb, pA, pB, K, 0, tid);
    CP_COMMIT();
    stage_load<IM>(sb + STAGE_BYTES, pA, pB, K, BK, tid);
    CP_COMMIT();

    for (int c = 0; c < nch; ++c) {
        if (c + 1 < nch) { CP_WAIT1(); } else { CP_WAIT0(); }  // stage c retired
        __syncthreads();   // stage-c visible to all; compute c-1 done everywhere
        if (c + 2 < nch) { // slot (c+2)%NSTAGE freed (last read at compute c-1)
            stage_load<IM>(sb + ((c + 2) % NSTAGE) * STAGE_BYTES, pA, pB,
                           K, (long)(c + 2) * BK, tid);
            CP_COMMIT();
        }

        const uint32_t stg = sb + (c % NSTAGE) * STAGE_BYTES;

        // B fragments for BOTH k-slices: 4 x ldmatrix.x4
        uint32_t bfr[4][4];
        #pragma unroll
        for (int j = 0; j < 4; ++j) {
            uint32_t boff = stg + 2 * TILE_BYTES + (bRow + j * 8) * ROW_BYTES
                            + bColB4;
            LDSM_X4(bfr[j][0], bfr[j][1], bfr[j][2], bfr[j][3], boff);
        }

        #pragma unroll
        for (int ks = 0; ks < 2; ++ks) {
            uint32_t ah[IM][4];
            #pragma unroll
            for (int i = 0; i < IM; ++i) {
                uint32_t aoff = stg + (aRow + i * 16) * ROW_BYTES + aColB + ks * 32;
                LDSM_X4(ah[i][0], ah[i][1], ah[i][2], ah[i][3], aoff);
            }
            #pragma unroll
            for (int i = 0; i < IM; ++i)
                #pragma unroll
                for (int j = 0; j < 4; ++j)
                    MMA_F16(acc[i][j], ah[i], bfr[j] + 2 * ks);
        }
    }

    #pragma unroll
    for (int i = 0; i < IM; ++i) {
        const long r0 = rowBase + wr * (IM * 16) + i * 16 + (lane >> 2);
        #pragma unroll
        for (int j = 0; j < 4; ++j) {
            const int col = wc * 32 + j * 8 + (lane & 3) * 2;
            if (Ohi != nullptr) {
                *(uint32_t*)(Ohi + r0 * Nc + colBase + col) =
                    packh2(acc[i][j][0], acc[i][j][1]);
                *(uint32_t*)(Ohi + (r0 + 8) * Nc + colBase + col) =
                    packh2(acc[i][j][2], acc[i][j][3]);
            } else {
                float b0 = 0.f, b1 = 0.f;
                if (bias != nullptr) {
                    b0 = bias[colBase + col];
                    b1 = bias[colBase + col + 1];
                }
                *(float2*)(C + r0 * Nc + colBase + col) =
                    make_float2(acc[i][j][0] + b0, acc[i][j][1] + b1);
                *(float2*)(C + (r0 + 8) * Nc + colBase + col) =
                    make_float2(acc[i][j][2] + b0, acc[i][j][3] + b1);
            }
        }
    }
}

// ---------------------------------------------------------------------------
// fused prep: round x to fp16 + transpose/round both weight matrices.
// ---------------------------------------------------------------------------
#define RB ((ROWS * DIMM) / 256)           // 24576
#define WQB ((QKVC / 32) * (DIMM / 32))    // 1728

__device__ __forceinline__ void tpose_tile(
    const float* __restrict__ W, __half* __restrict__ T,
    int K, int Nc, int n0, int k0, float t[32][33])
{
    const int lx = threadIdx.x & 31;
    const int ly = threadIdx.x >> 5;
    #pragma unroll
    for (int r = ly; r < 32; r += 8)
        t[r][lx] = W[(long)(k0 + r) * Nc + n0 + lx];
    __syncthreads();
    #pragma unroll
    for (int r = ly; r < 32; r += 8)
        T[(long)(n0 + r) * K + k0 + lx] = __float2half_rn(t[lx][r]);
}

__global__ __launch_bounds__(256)
void prep_kernel(const float* __restrict__ x, __half* __restrict__ xh,
                 const float* __restrict__ Wqkv, __half* __restrict__ wqh,
                 const float* __restrict__ Wo, __half* __restrict__ woh)
{
    __shared__ float t[32][33];
    const int b = blockIdx.x;
    if (b < RB) {
        const int i = b * 256 + threadIdx.x;
        xh[i] = __float2half_rn(x[i]);
    } else if (b < RB + WQB) {
        const int bb = b - RB;
        tpose_tile(Wqkv, wqh, DIMM, QKVC,
                   (bb % (QKVC / 32)) * 32, (bb / (QKVC / 32)) * 32, t);
    } else {
        const int bb = b - RB - WQB;
        tpose_tile(Wo, woh, DIMM, DIMM,
                   (bb % (DIMM / 32)) * 32, (bb / (DIMM / 32)) * 32, t);
    }
}

// ---------------------------------------------------------------------------
// fp16 flash attention. CTA = 128 queries of one (b,h) slice. 8 warps.
// 128-key stages (2 x 64-key sub-tiles per barrier). V fragments fetched with
// ldmatrix.x4.trans: lanes 16-31 address the same 16 key-rows at col+16B, so
// one x4 yields B-fragments for TWO adjacent dh-tiles (12 LDSM : 24 PV MMAs).
// ---------------------------------------------------------------------------
#define AT_STRIDE 112                       // bytes per smem row (48 fp16 + pad)
#define AT_Q_BYTES (128 * AT_STRIDE)        // 14336
#define AT_T_BYTES (64 * AT_STRIDE)         // 7168
#define AT_SUB (2 * AT_T_BYTES)             // 14336 (K, V for 64 keys)
#define AT_STAGE128 (2 * AT_SUB)            // 28672 (128 keys)
#define ATT_SMEM (AT_Q_BYTES + 2 * AT_STAGE128)   // 71680

__device__ __forceinline__ void at_stage64(
    uint32_t sdst, const __half* kh, const __half* vh, int key0, int tid)
{
    for (int i = tid; i < 384; i += 256) {
        const int r = i / 6, c = i % 6;
        const uint32_t off = r * AT_STRIDE + c * 16;
        const long gm = (long)(key0 + r) * DH + c * 8;
        CP_ASYNC16(sdst + off,              kh + gm);
        CP_ASYNC16(sdst + AT_T_BYTES + off, vh + gm);
    }
}

__global__ __launch_bounds__(256, 2)
void attn_mma(const __half* __restrict__ qkvhi, __half* __restrict__ Ch)
{
    extern __shared__ char smem[];
    const uint32_t sb = smem_u32(smem);
    const int tid = threadIdx.x;
    const int wid = tid >> 5;
    const int lane = tid & 31;
    const int slice = blockIdx.y;
    const int q0 = blockIdx.x << 7;

    const long base = (long)(slice >> 4) * HEAD_BLK + (long)(slice & 15) * SLICE_SZ;
    const __half* qh = qkvhi + base + (long)q0 * DH;
    const __half* kh = qkvhi + THIRD + base;
    const __half* vh = qkvhi + 2L * THIRD + base;

    // group 0: Q tile
    for (int i = tid; i < 768; i += 256) {
        const int r = i / 6, c = i % 6;
        CP_ASYNC16(sb + r * AT_STRIDE + c * 16, qh + (long)r * DH + c * 8);
    }
    CP_COMMIT();
    // group 1: 128-key stage 0
    at_stage64(sb + AT_Q_BYTES,          kh, vh, 0,  tid);
    at_stage64(sb + AT_Q_BYTES + AT_SUB, kh, vh, 64, tid);
    CP_COMMIT();
    CP_WAIT1();          // Q retired (this thread)
    __syncthreads();     // Q visible to all

    // Q fragments (kept in regs, pre-scaled by ATT_SCALE*log2e)
    uint32_t qhf[3][4];
    {
        const int aRow = wid * 16 + ((lane >> 3) & 1) * 8 + (lane & 7);
        const int aColB = (lane >> 4) * 16;
        const __half2 qs = __float2half2_rn(QSCALE);
        #pragma unroll
        for (int ks = 0; ks < 3; ++ks) {
            uint32_t addr = sb + aRow * AT_STRIDE + aColB + ks * 32;
            LDSM_X4(qhf[ks][0], qhf[ks][1], qhf[ks][2], qhf[ks][3], addr);
            #pragma unroll
            for (int r = 0; r < 4; ++r) {
                __half2 v = *(__half2*)&qhf[ks][r];
                v = __hmul2(v, qs);
                qhf[ks][r] = *(uint32_t*)&v;
            }
        }
    }

    float m1 = -INFINITY, m2 = -INFINITY, l1 = 0.f, l2 = 0.f;
    float o[6][4];
    #pragma unroll
    for (int n = 0; n < 6; ++n)
        #pragma unroll
        for (int r = 0; r < 4; ++r) o[n][r] = 0.f;

    const int kpair = lane >> 3;
    const int kRowOff = (kpair >> 1) * 8 + (lane & 7);
    const int kColB = (kpair & 1) * 16;
    // V x4.trans addressing: rows from lane&15, col window from lane>>4
    const int vRowOff = (lane & 7) + ((lane >> 3) & 1) * 8;
    const int vColB4 = (lane >> 4) * 16;

    for (int kt = 0; kt < 8; ++kt) {
        CP_WAIT0();        // stage kt (128 keys) retired for this thread
        __syncthreads();   // stage-kt visible; compute kt-1 done everywhere
        if (kt + 1 < 8) {
            const uint32_t dst = sb + AT_Q_BYTES + ((kt + 1) & 1) * AT_STAGE128;
            at_stage64(dst,          kh, vh, (kt + 1) * 128,      tid);
            at_stage64(dst + AT_SUB, kh, vh, (kt + 1) * 128 + 64, tid);
            CP_COMMIT();
        }

        #pragma unroll
        for (int sub = 0; sub < 2; ++sub) {
            const uint32_t stg = sb + AT_Q_BYTES + (kt & 1) * AT_STAGE128
                                 + sub * AT_SUB;

            // ---- S = Q K^T (pre-scaled; log2 domain) ----
            float s[8][4];
            #pragma unroll
            for (int j = 0; j < 8; ++j)
                #pragma unroll
                for (int r = 0; r < 4; ++r) s[j][r] = 0.f;

            #pragma unroll
            for (int g = 0; g < 4; ++g) {
                #pragma unroll
                for (int ks = 0; ks < 3; ++ks) {
                    const uint32_t ka = stg + (g * 16 + kRowOff) * AT_STRIDE
                                        + kColB + ks * 32;
                    uint32_t kb[4];
                    LDSM_X4(kb[0], kb[1], kb[2], kb[3], ka);
                    MMA_F16(s[2 * g],     qhf[ks], kb);
                    MMA_F16(s[2 * g + 1], qhf[ks], kb + 2);
                }
            }

            // ---- online softmax (exp2 domain) ----
            float mx1 = s[0][0], mx2 = s[0][2];
            #pragma unroll
            for (int j = 0; j < 8; ++j) {
                mx1 = fmaxf(mx1, fmaxf(s[j][0], s[j][1]));
                mx2 = fmaxf(mx2, fmaxf(s[j][2], s[j][3]));
            }
            mx1 = fmaxf(mx1, __shfl_xor_sync(0xffffffffu, mx1, 1));
            mx1 = fmaxf(mx1, __shfl_xor_sync(0xffffffffu, mx1, 2));
            mx2 = fmaxf(mx2, __shfl_xor_sync(0xffffffffu, mx2, 1));
            mx2 = fmaxf(mx2, __shfl_xor_sync(0xffffffffu, mx2, 2));

            const float nm1 = fmaxf(m1, mx1);
            const float nm2 = fmaxf(m2, mx2);
            const float e1 = ex2f(m1 - nm1);
            const float e2 = ex2f(m2 - nm2);
            m1 = nm1; m2 = nm2;

            float sum1 = 0.f, sum2 = 0.f;
            #pragma unroll
            for (int j = 0; j < 8; ++j) {
                s[j][0] = ex2f(s[j][0] - m1);
                s[j][1] = ex2f(s[j][1] - m1);
                s[j][2] = ex2f(s[j][2] - m2);
                s[j][3] = ex2f(s[j][3] - m2);
                sum1 += s[j][0] + s[j][1];
                sum2 += s[j][2] + s[j][3];
            }
            sum1 += __shfl_xor_sync(0xffffffffu, sum1, 1);
            sum1 += __shfl_xor_sync(0xffffffffu, sum1, 2);
            sum2 += __shfl_xor_sync(0xffffffffu, sum2, 1);
            sum2 += __shfl_xor_sync(0xffffffffu, sum2, 2);
            l1 = l1 * e1 + sum1;
            l2 = l2 * e2 + sum2;

            #pragma unroll
            for (int n = 0; n < 6; ++n) {
                o[n][0] *= e1; o[n][1] *= e1;
                o[n][2] *= e2; o[n][3] *= e2;
            }

            // ---- O += P V (x4.trans: one LDSM serves two dh-tiles) ----
            #pragma unroll
            for (int kk = 0; kk < 4; ++kk) {
                uint32_t ph[4];
                ph[0] = packh2(s[2 * kk][0],     s[2 * kk][1]);
                ph[1] = packh2(s[2 * kk][2],     s[2 * kk][3]);
                ph[2] = packh2(s[2 * kk + 1][0], s[2 * kk + 1][1]);
                ph[3] = packh2(s[2 * kk + 1][2], s[2 * kk + 1][3]);

                const uint32_t vrowA = stg + AT_T_BYTES
                                       + (kk * 16 + vRowOff) * AT_STRIDE + vColB4;
                #pragma unroll
                for (int n2 = 0; n2 < 3; ++n2) {
                    uint32_t vb[4];
                    LDSM_X4T(vb[0], vb[1], vb[2], vb[3], vrowA + n2 * 32);
                    MMA_F16(o[2 * n2],     ph, vb);
                    MMA_F16(o[2 * n2 + 1], ph, vb + 2);
                }
            }
        }
    }

    // ---- epilogue: write fp16 context at raw-reshape-flat offsets ----
    const float inv1 = 1.f / l1;
    const float inv2 = 1.f / l2;
    const long r1 = q0 + wid * 16 + (lane >> 2);
    const long r2 = r1 + 8;
    #pragma unroll
    for (int n = 0; n < 6; ++n) {
        const int col = n * 8 + (lane & 3) * 2;
        *(uint32_t*)(Ch + base + r1 * DH + col) =
            packh2(o[n][0] * inv1, o[n][1] * inv1);
        *(uint32_t*)(Ch + base + r2 * DH + col) =
            packh2(o[n][2] * inv2, o[n][3] * inv2);
    }
}

// ---------------------------------------------------------------------------
extern "C" void kernel_launch(void* const* d_in, const int* in_sizes, int n_in,
                              void* d_out, int out_size)
{
    (void)in_sizes; (void)n_in; (void)out_size;
    const float* x    = (const float*)d_in[0];
    const float* Wqkv = (const float*)d_in[1];
    const float* Wo   = (const float*)d_in[2];
    const float* bo   = (const float*)d_in[3];
    float* out = (float*)d_out;

    void *qkvhi, *xh, *ch, *wqh, *woh;
    cudaGetSymbolAddress(&qkvhi, g_qkvhi);
    cudaGetSymbolAddress(&xh, g_xh);
    cudaGetSymbolAddress(&ch, g_ch);
    cudaGetSymbolAddress(&wqh, g_wqh);
    cudaGetSymbolAddress(&woh, g_woh);

    cudaFuncSetAttribute(mma_gemm<4>, cudaFuncAttributeMaxDynamicSharedMemorySize,
                         GEMM_SMEM);
    cudaFuncSetAttribute(mma_gemm<2>, cudaFuncAttributeMaxDynamicSharedMemorySize,
                         GEMM_SMEM);
    cudaFuncSetAttribute(attn_mma, cudaFuncAttributeMaxDynamicSharedMemorySize,
                         ATT_SMEM);

    // 0) fused prep: round x, transpose+round Wqkv and Wo
    const int WOB = (DIMM / 32) * (DIMM / 32);   // 576
    prep_kernel<<<RB + WQB + WOB, 256>>>(
        x, (__half*)xh, Wqkv, (__half*)wqh, Wo, (__half*)woh);

    // 1) QKV projection (128-row tiles) -> fp16 qkv
    mma_gemm<4><<<dim3(QKVC / 128, ROWS / 128), 256, GEMM_SMEM>>>(
        (const __half*)xh, (const __half*)wqh,
        nullptr, nullptr, (__half*)qkvhi,
        ROWS, QKVC, DIMM);

    // 2) fp16 flash attention -> fp16 context
    attn_mma<<<dim3(NSEQ / 128, NB * HEADS), 256, ATT_SMEM>>>(
        (const __half*)qkvhi, (__half*)ch);

    // 3) output projection (64-row tiles to fix wave tail, +bias) -> fp32 out
    mma_gemm<2><<<dim3(DIMM / 128, ROWS / 64), 256, GEMM_SMEM>>>(
        (const __half*)ch, (const __half*)woh,
        bo, out, nullptr,
        ROWS, DIMM, DIMM);
}